// round 15
// baseline (speedup 1.0000x reference)
#include <cuda_runtime.h>
#include <cuda_fp16.h>
#include <mma.h>
#include <math.h>
#include <stdint.h>

using namespace nvcuda;

#define TT   512
#define BB   256
#define IND  248
#define KP   256
#define HID  1024
#define NCTA 128
#define CHUNK 512

// ---------------------------------------------------------------------------
// Device globals
// ---------------------------------------------------------------------------
__device__ float  g_xp[(size_t)TT * BB * HID];    // xproj result (fp32)
__device__ __half g_xh[(size_t)TT * BB * KP];     // x (fp16, padded)
__device__ __half g_wih[HID * KP];                // W_ih (fp16)
__device__ __half g_whh[HID * HID];               // W_hh (fp16)
__device__ __half g_hf[2][BB * HID];              // hidden (fp16), ping-pong
__device__ float  g_zp[16][TT * BB];              // per-n-block z partials
__device__ float  g_zsum[BB * TT];                // reduced z, [b][t]
__device__ unsigned g_flags[8 * 32];              // per-group arrival flags: [bb*32 + nb]

// ---------------------------------------------------------------------------
// helpers
// ---------------------------------------------------------------------------
__device__ __forceinline__ uint32_t smem_u32(const void* p) {
    uint32_t a;
    asm("{ .reg .u64 t; cvta.to.shared.u64 t, %1; cvt.u32.u64 %0, t; }" : "=r"(a) : "l"(p));
    return a;
}
__device__ __forceinline__ void cp16_ca(void* s, const void* g) {
    asm volatile("cp.async.ca.shared.global [%0], [%1], 16;" :: "r"(smem_u32(s)), "l"(g) : "memory");
}
__device__ __forceinline__ void cp16_cg(void* s, const void* g) {
    asm volatile("cp.async.cg.shared.global [%0], [%1], 16;" :: "r"(smem_u32(s)), "l"(g) : "memory");
}
#define CP_COMMIT() asm volatile("cp.async.commit_group;" ::: "memory")
#define CP_WAIT0()  asm volatile("cp.async.wait_group 0;" ::: "memory")
#define CP_WAIT1()  asm volatile("cp.async.wait_group 1;" ::: "memory")

__device__ __forceinline__ void flag_release(unsigned* p, unsigned v) {
    asm volatile("st.global.release.gpu.b32 [%0], %1;" :: "l"(p), "r"(v) : "memory");
}
__device__ __forceinline__ unsigned flag_acquire(const unsigned* p) {
    unsigned v;
    asm volatile("ld.global.acquire.gpu.b32 %0, [%1];" : "=r"(v) : "l"(p) : "memory");
    return v;
}

__device__ __forceinline__ float fast_tanh(float x) {
    float r;
    asm("tanh.approx.f32 %0, %1;" : "=f"(r) : "f"(x));
    return r;
}

// ---------------------------------------------------------------------------
// init: zero h(-1) and arrival flags
// ---------------------------------------------------------------------------
__global__ void init_kernel() {
    int i = blockIdx.x * blockDim.x + threadIdx.x;
    if (i < BB * HID / 8) ((uint4*)g_hf[0])[i] = make_uint4(0, 0, 0, 0);
    if (i < 8 * 32) g_flags[i] = 0;
}

// ---------------------------------------------------------------------------
// preps (vectorized, 8 elements/thread)
// ---------------------------------------------------------------------------
__global__ void prep_whh(const float* __restrict__ W_hh) {
    int i = blockIdx.x * blockDim.x + threadIdx.x;
    const float* src = W_hh + (size_t)i * 8;
    __half hb[8];
#pragma unroll
    for (int j = 0; j < 8; j++) hb[j] = __float2half(src[j]);
    *(uint4*)(g_whh + (size_t)i * 8) = *(uint4*)hb;
}
__global__ void prep_wih(const float* __restrict__ W_ih) {
    int i = blockIdx.x * blockDim.x + threadIdx.x;
    int row = i >> 5, g = i & 31;
    __half hb[8];
#pragma unroll
    for (int j = 0; j < 8; j++) {
        int col = g * 8 + j;
        hb[j] = __float2half((col < IND) ? W_ih[row * IND + col] : 0.0f);
    }
    *(uint4*)(g_wih + (size_t)row * KP + g * 8) = *(uint4*)hb;
}
__global__ void prep_x(const float* __restrict__ x) {
    size_t i = (size_t)blockIdx.x * blockDim.x + threadIdx.x;
    size_t row = i >> 5; int g = (int)(i & 31);
    __half hb[8];
    if (g < 31) {
        float4 v1 = __ldg((const float4*)(x + row * IND + g * 8));
        float4 v2 = __ldg((const float4*)(x + row * IND + g * 8 + 4));
        float v[8] = {v1.x, v1.y, v1.z, v1.w, v2.x, v2.y, v2.z, v2.w};
#pragma unroll
        for (int j = 0; j < 8; j++) hb[j] = __float2half(v[j]);
    } else {
#pragma unroll
        for (int j = 0; j < 8; j++) hb[j] = __float2half(0.0f);
    }
    *(uint4*)(g_xh + row * KP + g * 8) = *(uint4*)hb;
}

// ---------------------------------------------------------------------------
// xproj via wmma (fp16): out = x @ W_ih^T + b_ih + b_hh
//   CTA tile 32m x 128n; 8 warps (2m x 4n); K=256 in 4 chunks of 64.
// ---------------------------------------------------------------------------
__global__ void __launch_bounds__(256) xproj_tc(const float* __restrict__ b_ih,
                                               const float* __restrict__ b_hh) {
    extern __shared__ char smem[];
    __half (*sA)[32][72]  = (__half(*)[32][72])(smem);
    __half (*sB)[128][72] = (__half(*)[128][72])(smem + 9216);
    float (*sOut)[136]    = (float(*)[136])(smem + 46080);

    const int tid = threadIdx.x, wid = tid >> 5;
    const int nb = blockIdx.x, mb = blockIdx.y;
    const int wm = wid & 1, wn = wid >> 1;

    wmma::fragment<wmma::accumulator, 16, 16, 16, float> acc[2];
    wmma::fill_fragment(acc[0], 0.0f);
    wmma::fill_fragment(acc[1], 0.0f);

    auto issue = [&](int buf, int k0) {
#pragma unroll
        for (int j = 0; j < 5; j++) {
            const int idx = tid + j * 256;
            if (idx < 256) {
                const int r = idx >> 3, c8 = (idx & 7) * 8;
                cp16_cg(&sA[buf][r][c8], g_xh + (size_t)(mb * 32 + r) * KP + k0 + c8);
            } else if (idx < 1280) {
                const int i2 = idx - 256, r = i2 >> 3, c8 = (i2 & 7) * 8;
                cp16_ca(&sB[buf][r][c8], g_wih + (size_t)(nb * 128 + r) * KP + k0 + c8);
            }
        }
    };

    issue(0, 0); CP_COMMIT();
    for (int c = 0; c < 4; c++) {
        CP_WAIT0();
        __syncthreads();
        if (c < 3) { issue((c + 1) & 1, (c + 1) * 64); CP_COMMIT(); }
        const int buf = c & 1;
#pragma unroll
        for (int s = 0; s < 64; s += 16) {
            wmma::fragment<wmma::matrix_a, 16, 16, 16, __half, wmma::row_major> ah;
            wmma::load_matrix_sync(ah, &sA[buf][wm * 16][s], 72);
#pragma unroll
            for (int u = 0; u < 2; u++) {
                wmma::fragment<wmma::matrix_b, 16, 16, 16, __half, wmma::col_major> bh;
                wmma::load_matrix_sync(bh, &sB[buf][wn * 32 + u * 16][s], 72);
                wmma::mma_sync(acc[u], ah, bh, acc[u]);
            }
        }
    }
    __syncthreads();
    wmma::store_matrix_sync(&sOut[wm * 16][wn * 32],      acc[0], 136, wmma::mem_row_major);
    wmma::store_matrix_sync(&sOut[wm * 16][wn * 32 + 16], acc[1], 136, wmma::mem_row_major);
    __syncthreads();

    const int ml = tid & 31, grp = tid >> 5;
    const int n0 = nb * 128 + grp * 16;
    float r[16];
#pragma unroll
    for (int j = 0; j < 16; j++)
        r[j] = sOut[ml][grp * 16 + j] + b_ih[n0 + j] + b_hh[n0 + j];
    float* dst = g_xp + (size_t)(mb * 32 + ml) * HID + n0;
#pragma unroll
    for (int j = 0; j < 4; j++)
        *(float4*)(dst + 4 * j) = make_float4(r[4*j], r[4*j+1], r[4*j+2], r[4*j+3]);
}

// ---------------------------------------------------------------------------
// Persistent scan: 128 CTAs = 8 bb(32 rows) x 16 nb(64 cols), decoupled
// 16-CTA groups. W_hh slice (64x1024 fp16) persistent in smem; h streamed in
// 2 chunks of 512, double buffered (per-thread cp.async — measured best).
// Barrier = per-CTA release-store flags + parallel acquire-load spins
// (no atomic serialization); z-reduction moved AFTER flag publication.
// smem: sW[64][1032]h @0 (132096) | sA[2][32][520]h @132096 (66560)
//       sOut[32][72]f @198656 (9216) | sWout[64]f @207872 (256) = 208128
// ---------------------------------------------------------------------------
__global__ void __launch_bounds__(256, 1) step_tc(const float* __restrict__ W_out) {
    extern __shared__ char smem[];
    __half (*sW)[1032]    = (__half(*)[1032])(smem);
    __half (*sA)[32][520] = (__half(*)[32][520])(smem + 132096);
    float (*sOut)[72]     = (float(*)[72])(smem + 198656);
    float* sWout          = (float*)(smem + 207872);

    const int tid = threadIdx.x, wid = tid >> 5;
    const int nb = blockIdx.x & 15, bb = blockIdx.x >> 4;
    const int wm = wid & 1, wn = wid >> 1;           // 2m x 4n warp grid
    const int er = tid >> 3, ec = (tid & 7) * 8;     // epilogue: row (32), col-group

    // Load persistent W slice (64 x 1024) once
    for (int i = tid; i < 64 * 128; i += 256) {
        const int r = i >> 7, c8 = (i & 127) * 8;
        cp16_ca(&sW[r][c8], g_whh + (size_t)(nb * 64 + r) * HID + c8);
    }
    CP_COMMIT();
    if (tid < 64) sWout[tid] = W_out[nb * 64 + tid];
    CP_WAIT0();
    __syncthreads();

    unsigned* grpFlags = &g_flags[bb * 32];          // 16 words, own 128B region
    unsigned* myFlag   = &grpFlags[nb];

    for (int t = 0; t < TT; t++) {
        const __half* __restrict__ hsrc = g_hf[t & 1];

        auto issue = [&](int buf, int k0) {
#pragma unroll
            for (int j = 0; j < 8; j++) {            // 2048 cp16: 32 rows x 64/row
                const int idx = tid + j * 256;
                const int r = idx >> 6, c8 = (idx & 63) * 8;
                cp16_cg(&sA[buf][r][c8], hsrc + (size_t)(bb * 32 + r) * HID + k0 + c8);
            }
        };
        issue(0, 0); CP_COMMIT();
        issue(1, CHUNK); CP_COMMIT();

        // prefetch xp for the epilogue (overlaps h loads + MMAs)
        float xs[8];
        {
            const float* xpp = g_xp + ((size_t)t * BB + bb * 32 + er) * HID + nb * 64 + ec;
            float4 x1 = __ldcg((const float4*)xpp);
            float4 x2 = __ldcg((const float4*)(xpp + 4));
            xs[0]=x1.x; xs[1]=x1.y; xs[2]=x1.z; xs[3]=x1.w;
            xs[4]=x2.x; xs[5]=x2.y; xs[6]=x2.z; xs[7]=x2.w;
        }

        wmma::fragment<wmma::accumulator, 16, 16, 16, float> acc;
        wmma::fill_fragment(acc, 0.0f);

        CP_WAIT1();                                   // chunk 0 landed
        __syncthreads();
#pragma unroll
        for (int s = 0; s < CHUNK; s += 16) {
            wmma::fragment<wmma::matrix_a, 16, 16, 16, __half, wmma::row_major> ah;
            wmma::fragment<wmma::matrix_b, 16, 16, 16, __half, wmma::col_major> bh;
            wmma::load_matrix_sync(ah, &sA[0][wm * 16][s], 520);
            wmma::load_matrix_sync(bh, &sW[wn * 16][s], 1032);
            wmma::mma_sync(acc, ah, bh, acc);
        }
        CP_WAIT0();                                   // chunk 1 landed
        __syncthreads();
#pragma unroll
        for (int s = 0; s < CHUNK; s += 16) {
            wmma::fragment<wmma::matrix_a, 16, 16, 16, __half, wmma::row_major> ah;
            wmma::fragment<wmma::matrix_b, 16, 16, 16, __half, wmma::col_major> bh;
            wmma::load_matrix_sync(ah, &sA[1][wm * 16][s], 520);
            wmma::load_matrix_sync(bh, &sW[wn * 16][CHUNK + s], 1032);
            wmma::mma_sync(acc, ah, bh, acc);
        }
        wmma::store_matrix_sync(&sOut[wm * 16][wn * 16], acc, 72, wmma::mem_row_major);
        __syncthreads();

        // ---- epilogue: tanh + fp16 h store (z kept in regs for later) ----
        const int bglob = bb * 32 + er;
        __half hb[8];
        float z = 0.0f;
#pragma unroll
        for (int j = 0; j < 8; j++) {
            float f = fast_tanh(xs[j] + sOut[er][ec + j]);
            z += f * sWout[ec + j];
            hb[j] = __float2half(f);
        }
        *(uint4*)(g_hf[(t & 1) ^ 1] + (size_t)bglob * HID + nb * 64 + ec) = *(uint4*)hb;

        // ---- publish ASAP: all h stores done -> release flag ----
        __syncthreads();
        if (tid == 0) flag_release(myFlag, (unsigned)(t + 1));

        // off-critical-path: z reduce + store (hides peers' latency)
        z += __shfl_xor_sync(0xffffffffu, z, 1);
        z += __shfl_xor_sync(0xffffffffu, z, 2);
        z += __shfl_xor_sync(0xffffffffu, z, 4);
        if ((tid & 7) == 0) g_zp[nb][t * BB + bglob] = z;

        // ---- parallel spin: 16 threads, one flag each (acquire) ----
        if (tid < 16) {
            const unsigned tgt = (unsigned)(t + 1);
            while (flag_acquire(&grpFlags[tid]) < tgt) { }
        }
        __syncthreads();
    }
}

// ---------------------------------------------------------------------------
// reduce z partials: g_zsum[b][t] = sum_nb g_zp[nb][t*BB+b]
// ---------------------------------------------------------------------------
__global__ void reduce_z() {
    int idx = blockIdx.x * blockDim.x + threadIdx.x;
    int b = idx & 255, t = idx >> 8;
    float s = 0.0f;
#pragma unroll
    for (int p = 0; p < 16; p++) s += g_zp[p][idx];
    g_zsum[b * TT + t] = s;
}

// ---------------------------------------------------------------------------
// output scan
// ---------------------------------------------------------------------------
__global__ void out_kernel(const float* __restrict__ b_out,
                           const float* __restrict__ w_r,
                           const float* __restrict__ b_r,
                           float* __restrict__ out) {
    const int b = threadIdx.x;
    const float bo = b_out[0], wr = w_r[0], br = b_r[0];
    float o = 0.0f;
    for (int t4 = 0; t4 < TT; t4 += 4) {
        float4 z4 = *(const float4*)(g_zsum + b * TT + t4);
        float zz[4] = {z4.x, z4.y, z4.z, z4.w};
        float oo[4];
#pragma unroll
        for (int j = 0; j < 4; j++) {
            float arg = (t4 + j == 0) ? (zz[j] + bo) : (zz[j] + bo + wr * o + br);
            o = 1.0f / (1.0f + expf(-arg));
            oo[j] = o;
        }
        *(float4*)(out + b * TT + t4) = make_float4(oo[0], oo[1], oo[2], oo[3]);
    }
}

// ---------------------------------------------------------------------------
// Launch
// ---------------------------------------------------------------------------
extern "C" void kernel_launch(void* const* d_in, const int* in_sizes, int n_in,
                              void* d_out, int out_size) {
    const float* x     = (const float*)d_in[0];
    const float* W_ih  = (const float*)d_in[1];
    const float* b_ih  = (const float*)d_in[2];
    const float* W_hh  = (const float*)d_in[3];
    const float* b_hh  = (const float*)d_in[4];
    const float* W_out = (const float*)d_in[5];
    const float* b_out = (const float*)d_in[6];
    const float* w_r   = (const float*)d_in[7];
    const float* b_r   = (const float*)d_in[8];
    float* out = (float*)d_out;

    cudaFuncSetAttribute(step_tc,  cudaFuncAttributeMaxDynamicSharedMemorySize, 208128);
    cudaFuncSetAttribute(xproj_tc, cudaFuncAttributeMaxDynamicSharedMemorySize, 63488);

    init_kernel<<<128, 256>>>();
    prep_whh<<<(HID * HID / 8) / 256, 256>>>(W_hh);
    prep_wih<<<(HID * 32) / 256, 256>>>(W_ih);
    prep_x<<<(TT * BB * 32) / 256, 256>>>(x);
    xproj_tc<<<dim3(HID / 128, (TT * BB) / 32), 256, 63488>>>(b_ih, b_hh);
    step_tc<<<NCTA, 256, 208128>>>(W_out);
    reduce_z<<<(TT * BB) / 256, 256>>>();
    out_kernel<<<1, 256>>>(b_out, w_r, b_r, out);
}

// round 16
// speedup vs baseline: 1.2987x; 1.2987x over previous
#include <cuda_runtime.h>
#include <cuda_fp16.h>
#include <mma.h>
#include <math.h>
#include <stdint.h>

using namespace nvcuda;

#define TT   512
#define BB   256
#define IND  248
#define KP   256
#define HID  1024
#define NCTA 128
#define CHUNK 512

// ---------------------------------------------------------------------------
// Device globals
// ---------------------------------------------------------------------------
__device__ __half g_xp[(size_t)TT * BB * HID];    // xproj result (fp16)
__device__ __half g_xh[(size_t)TT * BB * KP];     // x (fp16, padded)
__device__ __half g_wih[HID * KP];                // W_ih (fp16)
__device__ __half g_whh[HID * HID];               // W_hh (fp16)
__device__ __half g_hf[2][BB * HID];              // hidden (fp16), ping-pong
__device__ float  g_zp[16][TT * BB];              // per-n-block z partials
__device__ float  g_zsum[BB * TT];                // reduced z, [b][t]
__device__ unsigned g_cnt[8 * 32];                // per-bb-group barrier, 128B apart

// ---------------------------------------------------------------------------
// helpers
// ---------------------------------------------------------------------------
__device__ __forceinline__ uint32_t smem_u32(const void* p) {
    uint32_t a;
    asm("{ .reg .u64 t; cvta.to.shared.u64 t, %1; cvt.u32.u64 %0, t; }" : "=r"(a) : "l"(p));
    return a;
}
__device__ __forceinline__ void cp16_ca(void* s, const void* g) {
    asm volatile("cp.async.ca.shared.global [%0], [%1], 16;" :: "r"(smem_u32(s)), "l"(g) : "memory");
}
__device__ __forceinline__ void cp16_cg(void* s, const void* g) {
    asm volatile("cp.async.cg.shared.global [%0], [%1], 16;" :: "r"(smem_u32(s)), "l"(g) : "memory");
}
#define CP_COMMIT() asm volatile("cp.async.commit_group;" ::: "memory")
#define CP_WAIT0()  asm volatile("cp.async.wait_group 0;" ::: "memory")
#define CP_WAIT1()  asm volatile("cp.async.wait_group 1;" ::: "memory")

__device__ __forceinline__ float fast_tanh(float x) {
    float r;
    asm("tanh.approx.f32 %0, %1;" : "=f"(r) : "f"(x));
    return r;
}

// ---------------------------------------------------------------------------
// init: zero h(-1) and barrier counters
// ---------------------------------------------------------------------------
__global__ void init_kernel() {
    int i = blockIdx.x * blockDim.x + threadIdx.x;
    if (i < BB * HID / 8) ((uint4*)g_hf[0])[i] = make_uint4(0, 0, 0, 0);
    if (i < 8 * 32) g_cnt[i] = 0;
}

// ---------------------------------------------------------------------------
// preps (vectorized, 8 elements/thread)
// ---------------------------------------------------------------------------
__global__ void prep_whh(const float* __restrict__ W_hh) {
    int i = blockIdx.x * blockDim.x + threadIdx.x;
    const float* src = W_hh + (size_t)i * 8;
    __half hb[8];
#pragma unroll
    for (int j = 0; j < 8; j++) hb[j] = __float2half(src[j]);
    *(uint4*)(g_whh + (size_t)i * 8) = *(uint4*)hb;
}
__global__ void prep_wih(const float* __restrict__ W_ih) {
    int i = blockIdx.x * blockDim.x + threadIdx.x;
    int row = i >> 5, g = i & 31;
    __half hb[8];
#pragma unroll
    for (int j = 0; j < 8; j++) {
        int col = g * 8 + j;
        hb[j] = __float2half((col < IND) ? W_ih[row * IND + col] : 0.0f);
    }
    *(uint4*)(g_wih + (size_t)row * KP + g * 8) = *(uint4*)hb;
}
__global__ void prep_x(const float* __restrict__ x) {
    size_t i = (size_t)blockIdx.x * blockDim.x + threadIdx.x;
    size_t row = i >> 5; int g = (int)(i & 31);
    __half hb[8];
    if (g < 31) {
        float4 v1 = __ldg((const float4*)(x + row * IND + g * 8));
        float4 v2 = __ldg((const float4*)(x + row * IND + g * 8 + 4));
        float v[8] = {v1.x, v1.y, v1.z, v1.w, v2.x, v2.y, v2.z, v2.w};
#pragma unroll
        for (int j = 0; j < 8; j++) hb[j] = __float2half(v[j]);
    } else {
#pragma unroll
        for (int j = 0; j < 8; j++) hb[j] = __float2half(0.0f);
    }
    *(uint4*)(g_xh + row * KP + g * 8) = *(uint4*)hb;
}

// ---------------------------------------------------------------------------
// xproj via wmma (fp16): out = x @ W_ih^T + b_ih + b_hh  -> stored as fp16
//   CTA tile 32m x 128n; 8 warps (2m x 4n); K=256 in 4 chunks of 64.
// ---------------------------------------------------------------------------
__global__ void __launch_bounds__(256) xproj_tc(const float* __restrict__ b_ih,
                                               const float* __restrict__ b_hh) {
    extern __shared__ char smem[];
    __half (*sA)[32][72]  = (__half(*)[32][72])(smem);
    __half (*sB)[128][72] = (__half(*)[128][72])(smem + 9216);
    float (*sOut)[136]    = (float(*)[136])(smem + 46080);

    const int tid = threadIdx.x, wid = tid >> 5;
    const int nb = blockIdx.x, mb = blockIdx.y;
    const int wm = wid & 1, wn = wid >> 1;

    wmma::fragment<wmma::accumulator, 16, 16, 16, float> acc[2];
    wmma::fill_fragment(acc[0], 0.0f);
    wmma::fill_fragment(acc[1], 0.0f);

    auto issue = [&](int buf, int k0) {
#pragma unroll
        for (int j = 0; j < 5; j++) {
            const int idx = tid + j * 256;
            if (idx < 256) {
                const int r = idx >> 3, c8 = (idx & 7) * 8;
                cp16_cg(&sA[buf][r][c8], g_xh + (size_t)(mb * 32 + r) * KP + k0 + c8);
            } else if (idx < 1280) {
                const int i2 = idx - 256, r = i2 >> 3, c8 = (i2 & 7) * 8;
                cp16_ca(&sB[buf][r][c8], g_wih + (size_t)(nb * 128 + r) * KP + k0 + c8);
            }
        }
    };

    issue(0, 0); CP_COMMIT();
    for (int c = 0; c < 4; c++) {
        CP_WAIT0();
        __syncthreads();
        if (c < 3) { issue((c + 1) & 1, (c + 1) * 64); CP_COMMIT(); }
        const int buf = c & 1;
#pragma unroll
        for (int s = 0; s < 64; s += 16) {
            wmma::fragment<wmma::matrix_a, 16, 16, 16, __half, wmma::row_major> ah;
            wmma::load_matrix_sync(ah, &sA[buf][wm * 16][s], 72);
#pragma unroll
            for (int u = 0; u < 2; u++) {
                wmma::fragment<wmma::matrix_b, 16, 16, 16, __half, wmma::col_major> bh;
                wmma::load_matrix_sync(bh, &sB[buf][wn * 32 + u * 16][s], 72);
                wmma::mma_sync(acc[u], ah, bh, acc[u]);
            }
        }
    }
    __syncthreads();
    wmma::store_matrix_sync(&sOut[wm * 16][wn * 32],      acc[0], 136, wmma::mem_row_major);
    wmma::store_matrix_sync(&sOut[wm * 16][wn * 32 + 16], acc[1], 136, wmma::mem_row_major);
    __syncthreads();

    const int ml = tid & 31, grp = tid >> 5;
    const int n0 = nb * 128 + grp * 16;
    __half r[16];
#pragma unroll
    for (int j = 0; j < 16; j++)
        r[j] = __float2half(sOut[ml][grp * 16 + j] + b_ih[n0 + j] + b_hh[n0 + j]);
    __half* dst = g_xp + (size_t)(mb * 32 + ml) * HID + n0;
    *(uint4*)dst       = *(uint4*)r;
    *(uint4*)(dst + 8) = *(uint4*)(r + 8);
}

// ---------------------------------------------------------------------------
// Persistent scan: 128 CTAs = 8 bb(32 rows) x 16 nb(64 cols), decoupled
// 16-CTA groups (R12 skeleton — measured local optimum; sync untouched).
// W_hh slice (64x1024 fp16) persistent in smem; h streamed in 2 chunks of
// 512, double buffered via per-thread cp.async. xp now fp16 (half traffic).
// smem: sW[64][1032]h @0 (132096) | sA[2][32][520]h @132096 (66560)
//       sOut[32][72]f @198656 (9216) | sWout[64]f @207872 (256) = 208128
// ---------------------------------------------------------------------------
__global__ void __launch_bounds__(256, 1) step_tc(const float* __restrict__ W_out) {
    extern __shared__ char smem[];
    __half (*sW)[1032]    = (__half(*)[1032])(smem);
    __half (*sA)[32][520] = (__half(*)[32][520])(smem + 132096);
    float (*sOut)[72]     = (float(*)[72])(smem + 198656);
    float* sWout          = (float*)(smem + 207872);

    const int tid = threadIdx.x, wid = tid >> 5;
    const int nb = blockIdx.x & 15, bb = blockIdx.x >> 4;
    const int wm = wid & 1, wn = wid >> 1;           // 2m x 4n warp grid
    const int er = tid >> 3, ec = (tid & 7) * 8;     // epilogue: row (32), col-group

    // Load persistent W slice (64 x 1024) once
    for (int i = tid; i < 64 * 128; i += 256) {
        const int r = i >> 7, c8 = (i & 127) * 8;
        cp16_ca(&sW[r][c8], g_whh + (size_t)(nb * 64 + r) * HID + c8);
    }
    CP_COMMIT();
    if (tid < 64) sWout[tid] = W_out[nb * 64 + tid];
    CP_WAIT0();
    __syncthreads();

    unsigned* bar = &g_cnt[bb * 32];

    for (int t = 0; t < TT; t++) {
        const __half* __restrict__ hsrc = g_hf[t & 1];

        auto issue = [&](int buf, int k0) {
#pragma unroll
            for (int j = 0; j < 8; j++) {            // 2048 cp16: 32 rows x 64/row
                const int idx = tid + j * 256;
                const int r = idx >> 6, c8 = (idx & 63) * 8;
                cp16_cg(&sA[buf][r][c8], hsrc + (size_t)(bb * 32 + r) * HID + k0 + c8);
            }
        };
        issue(0, 0); CP_COMMIT();
        issue(1, CHUNK); CP_COMMIT();

        // prefetch xp (fp16) for the epilogue (overlaps h loads + MMAs)
        float xs[8];
        {
            const __half* xpp = g_xp + ((size_t)t * BB + bb * 32 + er) * HID + nb * 64 + ec;
            uint4 xv = __ldcg((const uint4*)xpp);
            const __half2* xh2 = (const __half2*)&xv;
#pragma unroll
            for (int j = 0; j < 4; j++) {
                float2 f2 = __half22float2(xh2[j]);
                xs[2 * j] = f2.x; xs[2 * j + 1] = f2.y;
            }
        }

        wmma::fragment<wmma::accumulator, 16, 16, 16, float> acc;
        wmma::fill_fragment(acc, 0.0f);

        CP_WAIT1();                                   // chunk 0 landed
        __syncthreads();
#pragma unroll
        for (int s = 0; s < CHUNK; s += 16) {
            wmma::fragment<wmma::matrix_a, 16, 16, 16, __half, wmma::row_major> ah;
            wmma::fragment<wmma::matrix_b, 16, 16, 16, __half, wmma::col_major> bh;
            wmma::load_matrix_sync(ah, &sA[0][wm * 16][s], 520);
            wmma::load_matrix_sync(bh, &sW[wn * 16][s], 1032);
            wmma::mma_sync(acc, ah, bh, acc);
        }
        CP_WAIT0();                                   // chunk 1 landed
        __syncthreads();
#pragma unroll
        for (int s = 0; s < CHUNK; s += 16) {
            wmma::fragment<wmma::matrix_a, 16, 16, 16, __half, wmma::row_major> ah;
            wmma::fragment<wmma::matrix_b, 16, 16, 16, __half, wmma::col_major> bh;
            wmma::load_matrix_sync(ah, &sA[1][wm * 16][s], 520);
            wmma::load_matrix_sync(bh, &sW[wn * 16][CHUNK + s], 1032);
            wmma::mma_sync(acc, ah, bh, acc);
        }
        wmma::store_matrix_sync(&sOut[wm * 16][wn * 16], acc, 72, wmma::mem_row_major);
        __syncthreads();

        // ---- epilogue: tanh + fp16 h store + z partial ----
        const int bglob = bb * 32 + er;
        __half hb[8];
        float z = 0.0f;
#pragma unroll
        for (int j = 0; j < 8; j++) {
            float f = fast_tanh(xs[j] + sOut[er][ec + j]);
            z += f * sWout[ec + j];
            hb[j] = __float2half(f);
        }
        *(uint4*)(g_hf[(t & 1) ^ 1] + (size_t)bglob * HID + nb * 64 + ec) = *(uint4*)hb;

        // reduce z across the 8 lanes covering this row
        z += __shfl_xor_sync(0xffffffffu, z, 1);
        z += __shfl_xor_sync(0xffffffffu, z, 2);
        z += __shfl_xor_sync(0xffffffffu, z, 4);
        if ((tid & 7) == 0) g_zp[nb][t * BB + bglob] = z;

        // ---- per-bb-group barrier (16 CTAs, fully decoupled groups) ----
        __syncthreads();
        if (tid == 0) {
            __threadfence();                          // release h stores (cumulative)
            atomicAdd(bar, 1u);
            const unsigned tgt = 16u * (unsigned)(t + 1);
            while (*(volatile unsigned*)bar < tgt) { }
            __threadfence();                          // acquire peers' h stores
        }
        __syncthreads();
    }
}

// ---------------------------------------------------------------------------
// reduce z partials: g_zsum[b][t] = sum_nb g_zp[nb][t*BB+b]
// ---------------------------------------------------------------------------
__global__ void reduce_z() {
    int idx = blockIdx.x * blockDim.x + threadIdx.x;
    int b = idx & 255, t = idx >> 8;
    float s = 0.0f;
#pragma unroll
    for (int p = 0; p < 16; p++) s += g_zp[p][idx];
    g_zsum[b * TT + t] = s;
}

// ---------------------------------------------------------------------------
// output scan
// ---------------------------------------------------------------------------
__global__ void out_kernel(const float* __restrict__ b_out,
                           const float* __restrict__ w_r,
                           const float* __restrict__ b_r,
                           float* __restrict__ out) {
    const int b = threadIdx.x;
    const float bo = b_out[0], wr = w_r[0], br = b_r[0];
    float o = 0.0f;
    for (int t4 = 0; t4 < TT; t4 += 4) {
        float4 z4 = *(const float4*)(g_zsum + b * TT + t4);
        float zz[4] = {z4.x, z4.y, z4.z, z4.w};
        float oo[4];
#pragma unroll
        for (int j = 0; j < 4; j++) {
            float arg = (t4 + j == 0) ? (zz[j] + bo) : (zz[j] + bo + wr * o + br);
            o = 1.0f / (1.0f + __expf(-arg));
            oo[j] = o;
        }
        *(float4*)(out + b * TT + t4) = make_float4(oo[0], oo[1], oo[2], oo[3]);
    }
}

// ---------------------------------------------------------------------------
// Launch
// ---------------------------------------------------------------------------
extern "C" void kernel_launch(void* const* d_in, const int* in_sizes, int n_in,
                              void* d_out, int out_size) {
    const float* x     = (const float*)d_in[0];
    const float* W_ih  = (const float*)d_in[1];
    const float* b_ih  = (const float*)d_in[2];
    const float* W_hh  = (const float*)d_in[3];
    const float* b_hh  = (const float*)d_in[4];
    const float* W_out = (const float*)d_in[5];
    const float* b_out = (const float*)d_in[6];
    const float* w_r   = (const float*)d_in[7];
    const float* b_r   = (const float*)d_in[8];
    float* out = (float*)d_out;

    cudaFuncSetAttribute(step_tc,  cudaFuncAttributeMaxDynamicSharedMemorySize, 208128);
    cudaFuncSetAttribute(xproj_tc, cudaFuncAttributeMaxDynamicSharedMemorySize, 63488);

    init_kernel<<<128, 256>>>();
    prep_whh<<<(HID * HID / 8) / 256, 256>>>(W_hh);
    prep_wih<<<(HID * 32) / 256, 256>>>(W_ih);
    prep_x<<<(TT * BB * 32) / 256, 256>>>(x);
    xproj_tc<<<dim3(HID / 128, (TT * BB) / 32), 256, 63488>>>(b_ih, b_hh);
    step_tc<<<NCTA, 256, 208128>>>(W_out);
    reduce_z<<<(TT * BB) / 256, 256>>>();
    out_kernel<<<1, 256>>>(b_out, w_r, b_r, out);
}